// round 5
// baseline (speedup 1.0000x reference)
#include <cuda_runtime.h>

#define B_ 2
#define N_ 4096
#define M_ 4096
#define K_ 2048
#define NN 8192          // B_*N_ flattened points
#define KTOP 50
#define CAND_CAP 3072

static __device__ unsigned g_min_pg[B_*N_];   // min over gt for each pred
static __device__ unsigned g_min_gp[B_*M_];   // min over pred for each gt
static __device__ unsigned g_min_cov[B_*K_];  // min over pred for each partial
static __device__ double   g_acc[8];          // 0:cham1 1:cham2 2:cov 3:emd 4:unif 5:spread 6:rep
static __device__ float4   g_pts4[NN];        // packed pred points for uniformity
static __device__ float    g_sortP[3*NN];
static __device__ float    g_sortG[3*NN];

// ---------------------------------------------------------------- helpers
__device__ __forceinline__ void block_add_to_acc(float v, int slot) {
    for (int o = 16; o; o >>= 1) v += __shfl_xor_sync(0xFFFFFFFFu, v, o);
    __shared__ float sw[32];
    int lane = threadIdx.x & 31, wid = threadIdx.x >> 5;
    if (lane == 0) sw[wid] = v;
    __syncthreads();
    if (threadIdx.x == 0) {
        float s = 0.f;
        int nw = (blockDim.x + 31) >> 5;
        for (int w = 0; w < nw; w++) s += sw[w];
        atomicAdd(&g_acc[slot], (double)s);
    }
}

__device__ __forceinline__ unsigned* min_sel(int which) {
    return which == 0 ? g_min_pg : (which == 1 ? g_min_gp : g_min_cov);
}

// ---------------------------------------------------------------- init
__global__ void init_kernel() {
    int i = blockIdx.x * 256 + threadIdx.x;
    if (i < B_*N_) g_min_pg[i]  = 0x7F800000u;
    if (i < B_*M_) g_min_gp[i]  = 0x7F800000u;
    if (i < B_*K_) g_min_cov[i] = 0x7F800000u;
    if (i < 8)     g_acc[i] = 0.0;
}

__global__ void pack_kernel(const float* __restrict__ pred) {
    int i = blockIdx.x * 256 + threadIdx.x;
    if (i < NN) g_pts4[i] = make_float4(pred[3*i], pred[3*i+1], pred[3*i+2], 0.f);
}

// ---------------------------------------------------------------- row-min pairwise sq dist
// Each thread owns one A point; scans a chunk of B points staged as float4 in smem
// (broadcast LDS.128). Two independent min accumulators break the FMNMX chain.
__global__ void rowmin_kernel(const float* __restrict__ A, const float* __restrict__ Bp,
                              int nA, int nB, int chunk, int which) {
    __shared__ float4 sb[128];
    int b = blockIdx.z;
    const float* Ab = A  + (size_t)b * nA * 3;
    const float* Bb = Bp + ((size_t)b * nB + (size_t)blockIdx.y * chunk) * 3;
    int i = blockIdx.x * 128 + threadIdx.x;
    float ax = Ab[3*i], ay = Ab[3*i+1], az = Ab[3*i+2];
    float best0 = __int_as_float(0x7F800000);
    float best1 = best0;
    for (int t = 0; t < chunk; t += 128) {
        __syncthreads();
        const float* src = Bb + 3*(t + threadIdx.x);
        sb[threadIdx.x] = make_float4(src[0], src[1], src[2], 0.f);
        __syncthreads();
#pragma unroll 16
        for (int j = 0; j < 128; j += 2) {
            float4 q0 = sb[j], q1 = sb[j+1];
            float dx0 = ax - q0.x, dy0 = ay - q0.y, dz0 = az - q0.z;
            float dx1 = ax - q1.x, dy1 = ay - q1.y, dz1 = az - q1.z;
            float dd0 = fmaf(dx0, dx0, fmaf(dy0, dy0, dz0*dz0));
            float dd1 = fmaf(dx1, dx1, fmaf(dy1, dy1, dz1*dz1));
            best0 = fminf(best0, dd0);
            best1 = fminf(best1, dd1);
        }
    }
    float best = fminf(best0, best1);
    atomicMin(&min_sel(which)[b*nA + i], __float_as_uint(best));
}

__global__ void summin_kernel(int which, int n, int do_sqrt, int slot) {
    int i = blockIdx.x * 256 + threadIdx.x;
    float v = 0.f;
    if (i < n) {
        v = __uint_as_float(min_sel(which)[i]);
        if (do_sqrt) v = sqrtf(v);
    }
    block_add_to_acc(v, slot);
}

// ---------------------------------------------------------------- EMD: bitonic column sort
__global__ void emd_sort_kernel(const float* __restrict__ pred, const float* __restrict__ gt) {
    __shared__ float a[NN];
    int which = blockIdx.x;           // 0..5
    int c = which % 3;
    const float* src = (which < 3) ? pred : gt;
    float* dst = (which < 3) ? (g_sortP + c*NN) : (g_sortG + c*NN);
    int tid = threadIdx.x;
    for (int i = tid; i < NN; i += 1024) a[i] = src[3*i + c];
    __syncthreads();
    for (int k = 2; k <= NN; k <<= 1)
        for (int j = k >> 1; j > 0; j >>= 1) {
            for (int i = tid; i < NN; i += 1024) {
                int ixj = i ^ j;
                if (ixj > i) {
                    float x = a[i], y = a[ixj];
                    bool up = ((i & k) == 0);
                    if ((x > y) == up) { a[i] = y; a[ixj] = x; }
                }
            }
            __syncthreads();
        }
    for (int i = tid; i < NN; i += 1024) dst[i] = a[i];
}

__global__ void emd_diff_kernel() {
    int i = blockIdx.x * 256 + threadIdx.x;
    float v = 0.f;
    if (i < 3*NN) { float d = g_sortP[i] - g_sortG[i]; v = d*d; }
    block_add_to_acc(v, 3);
}

// ---------------------------------------------------------------- uniformity: per-row 50-NN std
// Block handles 32 rows, 2 rows per pass sharing q-point loads.
// Exact top-50: exponent-bucket histogram -> candidate gather -> parallel rank-by-count.
#define PROCESS_HALF(H, DD)                                                      \
    {                                                                            \
        if (tid == 0) s_cnt = 0;                                                 \
        if (wid == 0) {                                                          \
            unsigned v8[8], loc = 0;                                             \
            _Pragma("unroll")                                                    \
            for (int b2 = 0; b2 < 8; b2++) { v8[b2] = s_hist[H][lane*8 + b2]; loc += v8[b2]; } \
            unsigned pre = loc;                                                  \
            for (int o = 1; o < 32; o <<= 1) {                                   \
                unsigned t2 = __shfl_up_sync(0xFFFFFFFFu, pre, o);               \
                if (lane >= o) pre += t2;                                        \
            }                                                                    \
            unsigned cum = pre - loc;                                            \
            int myE = 256;                                                       \
            _Pragma("unroll")                                                    \
            for (int b2 = 0; b2 < 8; b2++) {                                     \
                cum += v8[b2];                                                   \
                if ((int)cum >= KTOP && myE == 256) myE = lane*8 + b2;           \
            }                                                                    \
            for (int o = 16; o; o >>= 1) {                                       \
                int t3 = __shfl_xor_sync(0xFFFFFFFFu, myE, o);                   \
                myE = min(myE, t3);                                              \
            }                                                                    \
            if (lane == 0) s_E = (unsigned)myE;                                  \
        }                                                                        \
        __syncthreads();                                                         \
        unsigned E = s_E;                                                        \
        _Pragma("unroll")                                                        \
        for (int k = 0; k < 32; k++) {                                           \
            unsigned bin = __float_as_uint(DD[k]) >> 23;                         \
            if (bin <= E) {                                                      \
                unsigned pos = atomicAdd(&s_cnt, 1u);                            \
                if (pos < CAND_CAP) s_buf[pos] = DD[k];                          \
            }                                                                    \
        }                                                                        \
        __syncthreads();                                                         \
        int c = (int)min(s_cnt, (unsigned)CAND_CAP);                             \
        float t1 = 0.f, t2 = 0.f;                                                \
        for (int j = tid; j < c; j += 256) {                                     \
            float v = s_buf[j];                                                  \
            int rank = 0;                                                        \
            for (int k = 0; k < c; k++) {                                        \
                float w = s_buf[k];                                              \
                rank += (w < v) || (w == v && k < j);                            \
            }                                                                    \
            if (rank >= 1 && rank < KTOP) { t1 += sqrtf(v); t2 += v; }           \
        }                                                                        \
        for (int o = 16; o; o >>= 1) {                                           \
            t1 += __shfl_xor_sync(0xFFFFFFFFu, t1, o);                           \
            t2 += __shfl_xor_sync(0xFFFFFFFFu, t2, o);                           \
        }                                                                        \
        if (lane == 0) { s_r1[wid] = t1; s_r2[wid] = t2; }                       \
        __syncthreads();                                                         \
        if (tid == 0) {                                                          \
            double s1 = 0.0, s2 = 0.0;                                           \
            for (int w = 0; w < 8; w++) { s1 += (double)s_r1[w]; s2 += (double)s_r2[w]; } \
            double mean = s1 / 49.0;                                             \
            double var = (s2 - 49.0*mean*mean) / 48.0;                           \
            if (var < 0.0) var = 0.0;                                            \
            rowacc += sqrt(var);                                                 \
        }                                                                        \
    }

__global__ void __launch_bounds__(256) uniformity_kernel() {
    __shared__ float    s_buf[CAND_CAP];
    __shared__ unsigned s_hist[2][256];
    __shared__ unsigned s_cnt;
    __shared__ unsigned s_E;
    __shared__ float    s_r1[8], s_r2[8];
    int tid = threadIdx.x, lane = tid & 31, wid = tid >> 5;
    double rowacc = 0.0;   // meaningful only on tid==0

    for (int r = 0; r < 32; r += 2) {
        int row = blockIdx.x * 32 + r;
        float4 p0 = g_pts4[row], p1 = g_pts4[row + 1];
        s_hist[0][tid] = 0;
        s_hist[1][tid] = 0;
        __syncthreads();

        float d0[32], d1[32];
#pragma unroll
        for (int k = 0; k < 32; k++) {
            float4 q = g_pts4[k*256 + tid];
            float dx0 = p0.x - q.x, dy0 = p0.y - q.y, dz0 = p0.z - q.z;
            float dx1 = p1.x - q.x, dy1 = p1.y - q.y, dz1 = p1.z - q.z;
            d0[k] = fmaf(dx0, dx0, fmaf(dy0, dy0, dz0*dz0));
            d1[k] = fmaf(dx1, dx1, fmaf(dy1, dy1, dz1*dz1));
        }
        // exponent-bucket histograms, warp-aggregated
#pragma unroll
        for (int k = 0; k < 32; k++) {
            unsigned bin0 = __float_as_uint(d0[k]) >> 23;
            unsigned m0 = __match_any_sync(0xFFFFFFFFu, bin0);
            if (lane == __ffs(m0) - 1) atomicAdd(&s_hist[0][bin0], (unsigned)__popc(m0));
            unsigned bin1 = __float_as_uint(d1[k]) >> 23;
            unsigned m1 = __match_any_sync(0xFFFFFFFFu, bin1);
            if (lane == __ffs(m1) - 1) atomicAdd(&s_hist[1][bin1], (unsigned)__popc(m1));
        }
        __syncthreads();

        PROCESS_HALF(0, d0)
        __syncthreads();
        PROCESS_HALF(1, d1)
        __syncthreads();
    }
    if (tid == 0) atomicAdd(&g_acc[4], rowacc);
}

// ---------------------------------------------------------------- spread
__global__ void spread_kernel(const float* __restrict__ pred) {
    int b = blockIdx.x / 3, c = blockIdx.x % 3;
    const float* p = pred + (size_t)b * N_ * 3 + c;
    double s1 = 0.0, s2 = 0.0;
    for (int i = threadIdx.x; i < N_; i += 256) {
        double x = (double)p[3*i];
        s1 += x; s2 += x*x;
    }
    for (int o = 16; o; o >>= 1) {
        s1 += __shfl_xor_sync(0xFFFFFFFFu, s1, o);
        s2 += __shfl_xor_sync(0xFFFFFFFFu, s2, o);
    }
    __shared__ double sw1[8], sw2[8];
    int lane = threadIdx.x & 31, wid = threadIdx.x >> 5;
    if (lane == 0) { sw1[wid] = s1; sw2[wid] = s2; }
    __syncthreads();
    if (threadIdx.x == 0) {
        double a = 0, bb = 0;
        for (int w = 0; w < 8; w++) { a += sw1[w]; bb += sw2[w]; }
        double mean = a / (double)N_;
        double var = (bb - (double)N_ * mean * mean) / (double)(N_ - 1);
        if (var < 0.0) var = 0.0;
        atomicAdd(&g_acc[5], sqrt(var));
    }
}

// ---------------------------------------------------------------- repulsion
// NOTE: sample_idx arrives as int32 (JAX x64 disabled downcasts astype(int64)).
__global__ void repulsion_kernel(const float* __restrict__ pred,
                                 const int* __restrict__ sidx) {
    __shared__ float sp[200*3];
    int tid = threadIdx.x;
    for (int s = tid; s < 200; s += 256) {
        int b = s / 100, k = s % 100;
        int idx = sidx[k];
        if (idx < 0) idx = 0;
        if (idx >= N_) idx = N_ - 1;
        const float* src = pred + ((size_t)b * N_ + (size_t)idx) * 3;
        sp[3*s] = src[0]; sp[3*s+1] = src[1]; sp[3*s+2] = src[2];
    }
    __syncthreads();
    float sum = 0.f;
    for (int t = tid; t < 2*100*100; t += 256) {
        int b = t / 10000, rem = t % 10000, i = rem / 100, j = rem % 100;
        if (i != j) {
            const float* pi = &sp[(b*100 + i)*3];
            const float* pj = &sp[(b*100 + j)*3];
            float dx = pi[0]-pj[0], dy = pi[1]-pj[1], dz = pi[2]-pj[2];
            float dd = fmaf(dx, dx, fmaf(dy, dy, dz*dz));
            float rr = 0.01f - sqrtf(dd);
            if (rr > 0.f) sum += rr;
        }
    }
    block_add_to_acc(sum, 6);
}

// ---------------------------------------------------------------- finalize
__global__ void final_kernel(float* out) {
    double cham   = g_acc[0] / (double)(B_*N_) + g_acc[1] / (double)(B_*M_);
    double emd    = g_acc[3] / (double)(NN*3) * 0.1;
    double cov    = g_acc[2] / (double)(B_*K_) * 5.0;
    double unif   = g_acc[4] / (double)NN * 2.0;
    double sstd   = g_acc[5] / 6.0;
    double spread = 0.5 - sstd;
    spread = (spread > 0.0) ? spread * 10.0 : 0.0;
    double rep    = g_acc[6] / (double)(B_*100*100) * 5.0;
    out[0] = (float)(cham + emd + cov + unif + spread + rep);
}

// ---------------------------------------------------------------- launch
// Fork/join across streams so independent kernels become parallel graph branches.
extern "C" void kernel_launch(void* const* d_in, const int* in_sizes, int n_in,
                              void* d_out, int out_size) {
    const float* pred    = (const float*)d_in[0];
    const float* gt      = (const float*)d_in[1];
    const float* partial = (const float*)d_in[2];
    const int*   sidx    = (const int*)d_in[3];
    float* out = (float*)d_out;

    static cudaStream_t s1 = 0, s2 = 0, s3 = 0;
    static cudaEvent_t  evRoot = 0, ev1 = 0, ev2 = 0, ev3 = 0;
    if (s1 == 0) {
        cudaStreamCreateWithFlags(&s1, cudaStreamNonBlocking);
        cudaStreamCreateWithFlags(&s2, cudaStreamNonBlocking);
        cudaStreamCreateWithFlags(&s3, cudaStreamNonBlocking);
        cudaEventCreateWithFlags(&evRoot, cudaEventDisableTiming);
        cudaEventCreateWithFlags(&ev1, cudaEventDisableTiming);
        cudaEventCreateWithFlags(&ev2, cudaEventDisableTiming);
        cudaEventCreateWithFlags(&ev3, cudaEventDisableTiming);
    }

    init_kernel<<<32, 256>>>();
    pack_kernel<<<32, 256>>>(pred);
    cudaEventRecord(evRoot, 0);
    cudaStreamWaitEvent(s1, evRoot, 0);
    cudaStreamWaitEvent(s2, evRoot, 0);
    cudaStreamWaitEvent(s3, evRoot, 0);

    // stream 0: uniformity (the longest single kernel)
    uniformity_kernel<<<NN/32, 256>>>();

    // s1: the two big chamfer scans + their reductions (32-way j-split)
    rowmin_kernel<<<dim3(N_/128, 32, B_), 128, 0, s1>>>(pred, gt,   N_, M_, M_/32, 0);
    rowmin_kernel<<<dim3(M_/128, 32, B_), 128, 0, s1>>>(gt,   pred, M_, N_, N_/32, 1);
    summin_kernel<<<(B_*N_+255)/256, 256, 0, s1>>>(0, B_*N_, 0, 0);
    summin_kernel<<<(B_*M_+255)/256, 256, 0, s1>>>(1, B_*M_, 0, 1);
    cudaEventRecord(ev1, s1);

    // s2: coverage + small terms
    rowmin_kernel<<<dim3(K_/128, 32, B_), 128, 0, s2>>>(partial, pred, K_, N_, N_/32, 2);
    summin_kernel<<<(B_*K_+255)/256, 256, 0, s2>>>(2, B_*K_, 1, 2);
    spread_kernel<<<6, 256, 0, s2>>>(pred);
    repulsion_kernel<<<1, 256, 0, s2>>>(pred, sidx);
    cudaEventRecord(ev2, s2);

    // s3: EMD sort + diff
    emd_sort_kernel<<<6, 1024, 0, s3>>>(pred, gt);
    emd_diff_kernel<<<(3*NN+255)/256, 256, 0, s3>>>();
    cudaEventRecord(ev3, s3);

    // join back on stream 0
    cudaStreamWaitEvent(0, ev1, 0);
    cudaStreamWaitEvent(0, ev2, 0);
    cudaStreamWaitEvent(0, ev3, 0);
    final_kernel<<<1, 1>>>(out);
}